// round 9
// baseline (speedup 1.0000x reference)
#include <cuda_runtime.h>
#include <cuda_bf16.h>
#include <cstdint>

#define BDIM 8
#define LDIM 2048
#define DDIM 1024
#define CH   341
#define NP   384
#define NSEG 512
#define KTOT 3072
#define NCHUNK 48           // KTOT / 64

// ---------------- device scratch ----------------
__device__ __nv_bfloat16 g_hbf[BDIM * LDIM * DDIM];
__device__ __nv_bfloat16 g_Wbf[NP * KTOT];            // [c][k*1024+d]
__device__ float          g_w2p[NP];
__device__ float          g_b1p[NP];
__device__ float          g_logits[BDIM * LDIM];
__device__ int            g_count[BDIM * NSEG];
__device__ int            g_start[BDIM * NSEG];
__device__ int            g_len[BDIM];
__device__ float          g_pe[NSEG * DDIM];
__device__ int            g_fix_cnt;
__device__ int            g_fix_list[16384];

__device__ __forceinline__ uint32_t smem_u32(const void* p) {
    uint32_t a;
    asm("{ .reg .u64 t; cvta.to.shared.u64 t, %1; cvt.u32.u64 %0, t; }" : "=r"(a) : "l"(p));
    return a;
}

// ---------------- fused setup: convert hidden, quantize W, PE, init ----------
__global__ void k_setup(const float* __restrict__ h, float* __restrict__ scalars,
                        const float* __restrict__ w1, const float* __restrict__ b1,
                        const float* __restrict__ w2) {
    int idx = blockIdx.x * blockDim.x + threadIdx.x;
    // hidden fp32 -> bf16 (8 elems/thread)
    if (idx < BDIM * LDIM * DDIM / 8) {
        const float4* src = (const float4*)h;
        uint2* dst = (uint2*)g_hbf;
        float4 a = src[2 * idx], b = src[2 * idx + 1];
        __nv_bfloat162 p0 = __floats2bfloat162_rn(a.x, a.y);
        __nv_bfloat162 p1 = __floats2bfloat162_rn(a.z, a.w);
        __nv_bfloat162 p2 = __floats2bfloat162_rn(b.x, b.y);
        __nv_bfloat162 p3 = __floats2bfloat162_rn(b.z, b.w);
        uint2 o0, o1;
        o0.x = *reinterpret_cast<uint32_t*>(&p0);
        o0.y = *reinterpret_cast<uint32_t*>(&p1);
        o1.x = *reinterpret_cast<uint32_t*>(&p2);
        o1.y = *reinterpret_cast<uint32_t*>(&p3);
        dst[2 * idx] = o0;
        dst[2 * idx + 1] = o1;
    }
    if (idx < NP * KTOT) {
        int c = idx / KTOT, r = idx % KTOT;
        int k = r >> 10, d = r & 1023;
        float v = (c < CH) ? w1[((size_t)c * 1024 + d) * 3 + k] : 0.f;
        g_Wbf[idx] = __float2bfloat16(v);
    }
    if (idx < NSEG * DDIM) {
        int s = idx >> 10, d = idx & 1023;
        float freq = expf(-logf(10000.f) * (float)(d & ~1) / 1024.f);
        float ang = (float)s * freq;
        g_pe[idx] = (d & 1) ? cosf(ang) : sinf(ang);
    }
    if (idx < NP) {
        g_w2p[idx] = (idx < CH) ? w2[idx] : 0.f;
        g_b1p[idx] = (idx < CH) ? b1[idx] : 0.f;
    }
    if (idx < BDIM * LDIM) g_logits[idx] = 0.f;
    if (idx == 0) { g_fix_cnt = 0; scalars[0] = 0.f; scalars[1] = 0.f; }
}

// ---------------- conv GEMM: bf16 mma.sync, CTA 128x192, 4-stage ring ---------
// grid (16, 2, 8) = 256 CTAs. 8 warps = 4(M) x 2(N); warp tile 32 x 96.
#define A_OFF(s) ((unsigned)(s) * 16384u)
#define B_OFF(s) (65536u + (unsigned)(s) * 24576u)
#define SMEM_CONV 163840

__global__ __launch_bounds__(256) void k_conv(const float* __restrict__ dummy) {
    extern __shared__ __align__(128) char smem[];
    const uint32_t sb = smem_u32(smem);
    const int tid  = threadIdx.x;
    const int lane = tid & 31;
    const int wid  = tid >> 5;
    const int wm   = wid >> 1;          // 0..3
    const int wn   = wid & 1;           // 0..1
    const int b    = blockIdx.z;
    const int l0   = blockIdx.x * 128;
    const int n0   = blockIdx.y * 192;

    const __nv_bfloat16* hbf = g_hbf;
    const __nv_bfloat16* wbf = g_Wbf;

    auto load_stage = [&](int c, int s) {
        const int k  = c >> 4;
        const int d0 = (c & 15) * 64;
        const int kc = c * 64;
        const uint32_t abase = sb + A_OFF(s);
        const uint32_t bbase = sb + B_OFF(s);
#pragma unroll
        for (int i = 0; i < 4; i++) {               // A: 128 rows x 128B
            int idx = tid + i * 256;
            int r = idx >> 3, c8 = idx & 7;
            long grow = (long)b * LDIM + l0 + k + r;
            const __nv_bfloat16* src = hbf + grow * DDIM + d0 + c8 * 8;
            uint32_t dst = abase + (uint32_t)(r * 128 + ((c8 ^ (r & 7)) << 4));
            unsigned nb = (grow < (long)BDIM * LDIM) ? 16u : 0u;
            asm volatile("cp.async.cg.shared.global [%0], [%1], 16, %2;"
                         :: "r"(dst), "l"(src), "r"(nb) : "memory");
        }
#pragma unroll
        for (int i = 0; i < 6; i++) {               // B: 192 rows x 128B
            int idx = tid + i * 256;
            int r = idx >> 3, c8 = idx & 7;
            const __nv_bfloat16* src = wbf + (size_t)(n0 + r) * KTOT + kc + c8 * 8;
            uint32_t dst = bbase + (uint32_t)(r * 128 + ((c8 ^ (r & 7)) << 4));
            asm volatile("cp.async.cg.shared.global [%0], [%1], 16;"
                         :: "r"(dst), "l"(src) : "memory");
        }
        asm volatile("cp.async.commit_group;" ::: "memory");
    };

    float acc[2][12][4];
#pragma unroll
    for (int i = 0; i < 2; i++)
#pragma unroll
        for (int j = 0; j < 12; j++)
#pragma unroll
            for (int e = 0; e < 4; e++) acc[i][j][e] = 0.f;

    load_stage(0, 0);
    load_stage(1, 1);
    load_stage(2, 2);

    for (int c = 0; c < NCHUNK; c++) {
        const int s = c & 3;
        if (c + 3 < NCHUNK) {
            load_stage(c + 3, (c + 3) & 3);
            asm volatile("cp.async.wait_group 3;" ::: "memory");
        } else {
            asm volatile("cp.async.wait_group 0;" ::: "memory");
        }
        __syncthreads();

        const uint32_t abase = sb + A_OFF(s);
        const uint32_t bbase = sb + B_OFF(s);

#pragma unroll
        for (int kk = 0; kk < 4; kk++) {
            uint32_t af[2][4];
#pragma unroll
            for (int i = 0; i < 2; i++) {
                int row = wm * 32 + i * 16 + (lane & 15);
                int chk = kk * 2 + (lane >> 4);
                uint32_t addr = abase + (uint32_t)(row * 128 + ((chk ^ (row & 7)) << 4));
                asm volatile(
                    "ldmatrix.sync.aligned.m8n8.x4.shared.b16 {%0,%1,%2,%3}, [%4];"
                    : "=r"(af[i][0]), "=r"(af[i][1]), "=r"(af[i][2]), "=r"(af[i][3])
                    : "r"(addr));
            }
            uint32_t bf[12][2];
#pragma unroll
            for (int jp = 0; jp < 6; jp++) {
                int grp = lane >> 3;
                int nrow = wn * 96 + jp * 16 + (grp >> 1) * 8 + (lane & 7);
                int chk  = kk * 2 + (grp & 1);
                uint32_t addr = bbase + (uint32_t)(nrow * 128 + ((chk ^ (nrow & 7)) << 4));
                asm volatile(
                    "ldmatrix.sync.aligned.m8n8.x4.shared.b16 {%0,%1,%2,%3}, [%4];"
                    : "=r"(bf[jp * 2][0]), "=r"(bf[jp * 2][1]),
                      "=r"(bf[jp * 2 + 1][0]), "=r"(bf[jp * 2 + 1][1])
                    : "r"(addr));
            }
#pragma unroll
            for (int i = 0; i < 2; i++)
#pragma unroll
                for (int j = 0; j < 12; j++) {
                    asm volatile(
                        "mma.sync.aligned.m16n8k16.row.col.f32.bf16.bf16.f32 "
                        "{%0,%1,%2,%3}, {%4,%5,%6,%7}, {%8,%9}, {%0,%1,%2,%3};"
                        : "+f"(acc[i][j][0]), "+f"(acc[i][j][1]),
                          "+f"(acc[i][j][2]), "+f"(acc[i][j][3])
                        : "r"(af[i][0]), "r"(af[i][1]), "r"(af[i][2]), "r"(af[i][3]),
                          "r"(bf[j][0]), "r"(bf[j][1]));
                }
        }
        __syncthreads();
    }

    // ---- epilogue: relu(acc + b1) * w2 reduced per row ----
    float* red = (float*)smem;
    if (tid < 128) red[tid] = 0.f;
    __syncthreads();

    const int cbase = n0 + wn * 96 + (lane & 3) * 2;
#pragma unroll
    for (int i = 0; i < 2; i++) {
#pragma unroll
        for (int h = 0; h < 2; h++) {
            float s = 0.f;
#pragma unroll
            for (int j = 0; j < 12; j++) {
                int cc = cbase + j * 8;
                float v0 = acc[i][j][h * 2 + 0];
                float v1 = acc[i][j][h * 2 + 1];
                s += fmaxf(v0 + g_b1p[cc], 0.f) * g_w2p[cc];
                s += fmaxf(v1 + g_b1p[cc + 1], 0.f) * g_w2p[cc + 1];
            }
            int row = wm * 32 + i * 16 + h * 8 + (lane >> 2);
            atomicAdd(&red[row], s);
        }
    }
    __syncthreads();
    if (tid < 128) {
        int l = l0 + tid;
        if (l < LDIM - 2) atomicAdd(&g_logits[b * LDIM + l + 2], red[tid]);
    }
}

// ---------------- add b2, flag near-zero logits ----------------
__global__ void k_flag(const float* __restrict__ b2) {
    int idx = blockIdx.x * blockDim.x + threadIdx.x;
    if (idx < BDIM * (LDIM - 2)) {
        int b = idx / (LDIM - 2), l = idx % (LDIM - 2), p = l + 2;
        float v = g_logits[b * LDIM + p] + b2[0];
        g_logits[b * LDIM + p] = v;
        if (fabsf(v) < 0.3f) {
            int i = atomicAdd(&g_fix_cnt, 1);
            if (i < 16384) g_fix_list[i] = (b << 16) | p;
        }
    }
}

// ---------------- fp32 recompute of flagged logits (12 FMA chains) ----------
__global__ void k_fix(const float* __restrict__ hidden, const float* __restrict__ w1,
                      const float* __restrict__ b1, const float* __restrict__ w2,
                      const float* __restrict__ b2) {
    __shared__ float sred[256];
    int n = g_fix_cnt;
    if (n > 16384) n = 16384;
    for (int it = blockIdx.x; it < n; it += gridDim.x) {
        int e = g_fix_list[it];
        int b = e >> 16, p = e & 0xffff, l = p - 2;
        const float* hb = hidden + ((size_t)b * LDIM + l) * DDIM;
        float s = 0.f;
        for (int c = threadIdx.x; c < CH; c += 256) {
            float a0 = 0.f, a1 = 0.f, a2 = 0.f, a3 = 0.f;
            const float* wc = w1 + (size_t)c * 3072;
#pragma unroll 4
            for (int d = 0; d < 1024; d += 4) {
#pragma unroll
                for (int q = 0; q < 4; q++) {
                    a0 += hb[d + q] * wc[(d + q) * 3 + 0];
                    a1 += hb[1024 + d + q] * wc[(d + q) * 3 + 1];
                    a2 += hb[2048 + d + q] * wc[(d + q) * 3 + 2];
                }
            }
            s += fmaxf(a0 + a1 + a2 + a3 + b1[c], 0.f) * w2[c];
        }
        sred[threadIdx.x] = s;
        __syncthreads();
        for (int o = 128; o > 0; o >>= 1) {
            if (threadIdx.x < o) sred[threadIdx.x] += sred[threadIdx.x + o];
            __syncthreads();
        }
        if (threadIdx.x == 0) g_logits[b * LDIM + p] = sred[0] + b2[0];
        __syncthreads();
    }
}

// ---------------- per-batch scan: seg ids, counts, starts, short_mask --------
__global__ void k_scan(const float* __restrict__ mask, float* __restrict__ out_short,
                       float* __restrict__ out_scalars) {
    const int b = blockIdx.x;
    const int tid = threadIdx.x;
    __shared__ int sh_red[256];
    __shared__ unsigned char sh_hard[LDIM];
    __shared__ int sh_scan[256];
    __shared__ int sh_len;
    __shared__ int sh_count[NSEG];

    const float* mb = mask + b * LDIM;
    int ls = 0;
    for (int p = tid; p < LDIM; p += 256) ls += (mb[p] > 0.5f) ? 1 : 0;
    sh_red[tid] = ls;
    __syncthreads();
    for (int o = 128; o > 0; o >>= 1) {
        if (tid < o) sh_red[tid] += sh_red[tid + o];
        __syncthreads();
    }
    if (tid == 0) sh_len = sh_red[0];
    __syncthreads();
    const int len = sh_len;

    for (int p = tid; p < LDIM; p += 256) {
        int bit = (p >= 2 && p < len && g_logits[b * LDIM + p] > 0.f) ? 1 : 0;
        sh_hard[p] = (unsigned char)bit;
    }
    __syncthreads();
    if (tid == 0 && len < LDIM) sh_hard[len - 1] = 1;
    for (int s = tid; s < NSEG; s += 256) sh_count[s] = 0;
    __syncthreads();

    const int base = tid * 8;
    int t = 0;
    for (int q = 0; q < 8; q++) t += sh_hard[base + q];
    sh_scan[tid] = t;
    __syncthreads();
    for (int o = 1; o < 256; o <<= 1) {
        int v = sh_scan[tid];
        int u = (tid >= o) ? sh_scan[tid - o] : 0;
        __syncthreads();
        sh_scan[tid] = v + u;
        __syncthreads();
    }
    const int nb = sh_scan[255];
    int run = sh_scan[tid] - t;
    for (int q = 0; q < 8; q++) {
        int p = base + q;
        if (run < NSEG) {
            if (p == 0 || (p > 0 && sh_hard[p - 1])) {
                if (p == 0 || p > 0) g_start[b * NSEG + run] = (p == 0) ? 0 : p;
            }
            if (p < len) atomicAdd(&sh_count[run], 1);
        }
        run += sh_hard[p];
    }
    __syncthreads();
    for (int s = tid; s < NSEG; s += 256) g_count[b * NSEG + s] = sh_count[s];
    for (int s = tid; s < NSEG; s += 256) out_short[b * NSEG + s] = (s < nb) ? 1.f : 0.f;
    if (tid == 0) {
        g_len[b] = len;
        atomicAdd(&out_scalars[0], (float)nb);
        atomicAdd(&out_scalars[1], (float)len);
    }
}

// ---------------- direct segment-mean pooling + PE (one block per (b,s)) -----
__global__ __launch_bounds__(256) void k_pool2(const float* __restrict__ hidden,
                                               float* __restrict__ pooled) {
    const int s = blockIdx.x;
    const int b = blockIdx.y;
    const int tid = threadIdx.x;
    const int d = tid * 4;
    const int cnt = g_count[b * NSEG + s];
    float4 acc = make_float4(0.f, 0.f, 0.f, 0.f);
    if (cnt > 0) {
        const int start = g_start[b * NSEG + s];
        const float* hb = hidden + ((size_t)b * LDIM + start) * DDIM + d;
        for (int i = 0; i < cnt; i++) {
            float4 v = *(const float4*)(hb + (size_t)i * DDIM);
            acc.x += v.x; acc.y += v.y; acc.z += v.z; acc.w += v.w;
        }
    }
    float inv = 1.f / ((float)cnt + 1e-9f);
    const float4 pe = *(const float4*)(g_pe + s * DDIM + d);
    float4 o;
    o.x = acc.x * inv + pe.x;
    o.y = acc.y * inv + pe.y;
    o.z = acc.z * inv + pe.z;
    o.w = acc.w * inv + pe.w;
    *(float4*)(pooled + ((size_t)b * NSEG + s) * DDIM + d) = o;
}

// ---------------- launch ----------------
extern "C" void kernel_launch(void* const* d_in, const int* in_sizes, int n_in,
                              void* d_out, int out_size) {
    const float* hidden = (const float*)d_in[0];
    const float* amask  = (const float*)d_in[1];
    const float* w1     = (const float*)d_in[2];
    const float* b1     = (const float*)d_in[3];
    const float* w2     = (const float*)d_in[4];
    const float* b2     = (const float*)d_in[5];
    float* out = (float*)d_out;

    float* out_scalars = out + (out_size - BDIM * NSEG - 2);
    float* out_short   = out + (out_size - BDIM * NSEG);

    cudaFuncSetAttribute(k_conv, cudaFuncAttributeMaxDynamicSharedMemorySize, SMEM_CONV);

    k_setup<<<8192, 256>>>(hidden, out_scalars, w1, b1, w2);
    k_conv<<<dim3(16, 2, BDIM), 256, SMEM_CONV>>>(nullptr);
    k_flag<<<(BDIM * (LDIM - 2) + 255) / 256, 256>>>(b2);
    k_fix<<<32, 256>>>(hidden, w1, b1, w2, b2);
    k_scan<<<BDIM, 256>>>(amask, out_short, out_scalars);
    k_pool2<<<dim3(NSEG, BDIM), 256>>>(hidden, out);
}

// round 10
// speedup vs baseline: 2.6378x; 2.6378x over previous
#include <cuda_runtime.h>
#include <cuda_bf16.h>
#include <cstdint>

#define BDIM 8
#define LDIM 2048
#define DDIM 1024
#define CH   341
#define NP   384
#define NSEG 512
#define KTOT 3072
#define NCHUNK 48           // KTOT / 64

// ---------------- device scratch ----------------
__device__ __nv_bfloat16 g_hbf[BDIM * LDIM * DDIM];
__device__ __nv_bfloat16 g_Wbf[NP * KTOT];            // [c][k*1024+d]
__device__ float          g_w2p[NP];
__device__ float          g_b1p[NP];
__device__ float          g_logits[BDIM * LDIM];
__device__ unsigned short g_seg[BDIM * LDIM];
__device__ int            g_count[BDIM * NSEG];
__device__ int            g_len[BDIM];
__device__ float          g_pe[NSEG * DDIM];
__device__ int            g_fix_cnt;
__device__ int            g_fix_list[16384];

__device__ __forceinline__ uint32_t smem_u32(const void* p) {
    uint32_t a;
    asm("{ .reg .u64 t; cvta.to.shared.u64 t, %1; cvt.u32.u64 %0, t; }" : "=r"(a) : "l"(p));
    return a;
}

// ------- fused setup: zero out region, convert hidden, reorder W, PE, init ----
__global__ void k_setup(const float* __restrict__ h, float* __restrict__ out, int nzero,
                        const float* __restrict__ w1, const float* __restrict__ b1,
                        const float* __restrict__ w2) {
    int idx = blockIdx.x * blockDim.x + threadIdx.x;
    if (idx < nzero) out[idx] = 0.f;
    if (idx < BDIM * LDIM * DDIM / 8) {
        const float4* src = (const float4*)h;
        uint2* dst = (uint2*)g_hbf;
        float4 a = src[2 * idx], b = src[2 * idx + 1];
        __nv_bfloat162 p0 = __floats2bfloat162_rn(a.x, a.y);
        __nv_bfloat162 p1 = __floats2bfloat162_rn(a.z, a.w);
        __nv_bfloat162 p2 = __floats2bfloat162_rn(b.x, b.y);
        __nv_bfloat162 p3 = __floats2bfloat162_rn(b.z, b.w);
        uint2 o0, o1;
        o0.x = *reinterpret_cast<uint32_t*>(&p0);
        o0.y = *reinterpret_cast<uint32_t*>(&p1);
        o1.x = *reinterpret_cast<uint32_t*>(&p2);
        o1.y = *reinterpret_cast<uint32_t*>(&p3);
        dst[2 * idx] = o0;
        dst[2 * idx + 1] = o1;
    }
    if (idx < NP * KTOT) {
        int c = idx / KTOT, r = idx % KTOT;
        int k = r >> 10, d = r & 1023;
        float v = (c < CH) ? w1[((size_t)c * 1024 + d) * 3 + k] : 0.f;
        g_Wbf[idx] = __float2bfloat16(v);
    }
    if (idx < NSEG * DDIM) {
        int s = idx >> 10, d = idx & 1023;
        float freq = expf(-logf(10000.f) * (float)(d & ~1) / 1024.f);
        float ang = (float)s * freq;
        g_pe[idx] = (d & 1) ? cosf(ang) : sinf(ang);
    }
    if (idx < NP) {
        g_w2p[idx] = (idx < CH) ? w2[idx] : 0.f;
        g_b1p[idx] = (idx < CH) ? b1[idx] : 0.f;
    }
    if (idx < BDIM * LDIM) g_logits[idx] = 0.f;
    if (idx == 0) g_fix_cnt = 0;
}

// ---------------- conv GEMM: bf16 mma.sync, 3-stage, 2 CTA/SM (R7-exact) -----
__global__ __launch_bounds__(256, 2) void k_conv(const float* __restrict__ dummy) {
    extern __shared__ __align__(128) char smem[];
    const uint32_t sb = smem_u32(smem);
    const int tid  = threadIdx.x;
    const int lane = tid & 31;
    const int wid  = tid >> 5;
    const int wm   = wid >> 1;
    const int wn   = wid & 1;
    const int b    = blockIdx.z;
    const int l0   = blockIdx.x * 128;
    const int n0   = blockIdx.y * 128;

    const __nv_bfloat16* hbf = g_hbf;
    const __nv_bfloat16* wbf = g_Wbf;

    auto load_stage = [&](int c, int s) {
        const int k  = c >> 4;
        const int d0 = (c & 15) * 64;
        const int kc = c * 64;
        const uint32_t abase = sb + (unsigned)s * 16384u;
        const uint32_t bbase = sb + 49152u + (unsigned)s * 16384u;
#pragma unroll
        for (int i = 0; i < 4; i++) {
            int idx = tid + i * 256;
            int r = idx >> 3, c8 = idx & 7;
            long grow = (long)b * LDIM + l0 + k + r;
            const __nv_bfloat16* src = hbf + grow * DDIM + d0 + c8 * 8;
            uint32_t dst = abase + (uint32_t)(r * 128 + ((c8 ^ (r & 7)) << 4));
            unsigned nb = (grow < (long)BDIM * LDIM) ? 16u : 0u;
            asm volatile("cp.async.cg.shared.global [%0], [%1], 16, %2;"
                         :: "r"(dst), "l"(src), "r"(nb) : "memory");
        }
#pragma unroll
        for (int i = 0; i < 4; i++) {
            int idx = tid + i * 256;
            int r = idx >> 3, c8 = idx & 7;
            const __nv_bfloat16* src = wbf + (size_t)(n0 + r) * KTOT + kc + c8 * 8;
            uint32_t dst = bbase + (uint32_t)(r * 128 + ((c8 ^ (r & 7)) << 4));
            asm volatile("cp.async.cg.shared.global [%0], [%1], 16;"
                         :: "r"(dst), "l"(src) : "memory");
        }
        asm volatile("cp.async.commit_group;" ::: "memory");
    };

    float acc[2][8][4];
#pragma unroll
    for (int i = 0; i < 2; i++)
#pragma unroll
        for (int j = 0; j < 8; j++)
#pragma unroll
            for (int e = 0; e < 4; e++) acc[i][j][e] = 0.f;

    load_stage(0, 0);
    load_stage(1, 1);

    for (int c = 0; c < NCHUNK; c++) {
        const int s = c % 3;
        if (c + 2 < NCHUNK) {
            load_stage(c + 2, (c + 2) % 3);
            asm volatile("cp.async.wait_group 2;" ::: "memory");
        } else {
            asm volatile("cp.async.wait_group 0;" ::: "memory");
        }
        __syncthreads();

        const uint32_t abase = sb + (unsigned)s * 16384u;
        const uint32_t bbase = sb + 49152u + (unsigned)s * 16384u;

#pragma unroll
        for (int kk = 0; kk < 4; kk++) {
            uint32_t af[2][4];
#pragma unroll
            for (int i = 0; i < 2; i++) {
                int row = wm * 32 + i * 16 + (lane & 15);
                int chk = kk * 2 + (lane >> 4);
                uint32_t addr = abase + (uint32_t)(row * 128 + ((chk ^ (row & 7)) << 4));
                asm volatile(
                    "ldmatrix.sync.aligned.m8n8.x4.shared.b16 {%0,%1,%2,%3}, [%4];"
                    : "=r"(af[i][0]), "=r"(af[i][1]), "=r"(af[i][2]), "=r"(af[i][3])
                    : "r"(addr));
            }
            uint32_t bf[8][2];
#pragma unroll
            for (int jp = 0; jp < 4; jp++) {
                int grp = lane >> 3;
                int nrow = wn * 64 + jp * 16 + (grp >> 1) * 8 + (lane & 7);
                int chk  = kk * 2 + (grp & 1);
                uint32_t addr = bbase + (uint32_t)(nrow * 128 + ((chk ^ (nrow & 7)) << 4));
                asm volatile(
                    "ldmatrix.sync.aligned.m8n8.x4.shared.b16 {%0,%1,%2,%3}, [%4];"
                    : "=r"(bf[jp * 2][0]), "=r"(bf[jp * 2][1]),
                      "=r"(bf[jp * 2 + 1][0]), "=r"(bf[jp * 2 + 1][1])
                    : "r"(addr));
            }
#pragma unroll
            for (int i = 0; i < 2; i++)
#pragma unroll
                for (int j = 0; j < 8; j++) {
                    asm volatile(
                        "mma.sync.aligned.m16n8k16.row.col.f32.bf16.bf16.f32 "
                        "{%0,%1,%2,%3}, {%4,%5,%6,%7}, {%8,%9}, {%0,%1,%2,%3};"
                        : "+f"(acc[i][j][0]), "+f"(acc[i][j][1]),
                          "+f"(acc[i][j][2]), "+f"(acc[i][j][3])
                        : "r"(af[i][0]), "r"(af[i][1]), "r"(af[i][2]), "r"(af[i][3]),
                          "r"(bf[j][0]), "r"(bf[j][1]));
                }
        }
        __syncthreads();
    }

    float* red = (float*)smem;
    if (tid < 128) red[tid] = 0.f;
    __syncthreads();

    const int cbase = n0 + wn * 64 + (lane & 3) * 2;
#pragma unroll
    for (int i = 0; i < 2; i++) {
#pragma unroll
        for (int h = 0; h < 2; h++) {
            float s = 0.f;
#pragma unroll
            for (int j = 0; j < 8; j++) {
                int cc = cbase + j * 8;
                float v0 = acc[i][j][h * 2 + 0];
                float v1 = acc[i][j][h * 2 + 1];
                s += fmaxf(v0 + g_b1p[cc], 0.f) * g_w2p[cc];
                s += fmaxf(v1 + g_b1p[cc + 1], 0.f) * g_w2p[cc + 1];
            }
            int row = wm * 32 + i * 16 + h * 8 + (lane >> 2);
            atomicAdd(&red[row], s);
        }
    }
    __syncthreads();
    if (tid < 128) {
        int l = l0 + tid;
        if (l < LDIM - 2) atomicAdd(&g_logits[b * LDIM + l + 2], red[tid]);
    }
}

// ---------------- add b2, flag near-zero logits ----------------
__global__ void k_flag(const float* __restrict__ b2) {
    int idx = blockIdx.x * blockDim.x + threadIdx.x;
    if (idx < BDIM * (LDIM - 2)) {
        int b = idx / (LDIM - 2), l = idx % (LDIM - 2), p = l + 2;
        float v = g_logits[b * LDIM + p] + b2[0];
        g_logits[b * LDIM + p] = v;
        if (fabsf(v) < 0.3f) {
            int i = atomicAdd(&g_fix_cnt, 1);
            if (i < 16384) g_fix_list[i] = (b << 16) | p;
        }
    }
}

// ---------------- fp32 recompute of flagged logits (ILP chains) --------------
__global__ void k_fix(const float* __restrict__ hidden, const float* __restrict__ w1,
                      const float* __restrict__ b1, const float* __restrict__ w2,
                      const float* __restrict__ b2) {
    __shared__ float sred[256];
    int n = g_fix_cnt;
    if (n > 16384) n = 16384;
    for (int it = blockIdx.x; it < n; it += gridDim.x) {
        int e = g_fix_list[it];
        int b = e >> 16, p = e & 0xffff, l = p - 2;
        const float* hb = hidden + ((size_t)b * LDIM + l) * DDIM;
        float s = 0.f;
        for (int c = threadIdx.x; c < CH; c += 256) {
            float a0 = 0.f, a1 = 0.f, a2 = 0.f;
            const float* wc = w1 + (size_t)c * 3072;
#pragma unroll 4
            for (int d = 0; d < 1024; d++) {
                a0 += hb[d] * wc[d * 3 + 0];
                a1 += hb[1024 + d] * wc[d * 3 + 1];
                a2 += hb[2048 + d] * wc[d * 3 + 2];
            }
            s += fmaxf(a0 + a1 + a2 + b1[c], 0.f) * w2[c];
        }
        sred[threadIdx.x] = s;
        __syncthreads();
        for (int o = 128; o > 0; o >>= 1) {
            if (threadIdx.x < o) sred[threadIdx.x] += sred[threadIdx.x + o];
            __syncthreads();
        }
        if (threadIdx.x == 0) g_logits[b * LDIM + p] = sred[0] + b2[0];
        __syncthreads();
    }
}

// ---------------- per-batch scan (R7-exact) ----------------
__global__ void k_scan(const float* __restrict__ mask, float* __restrict__ out_short,
                       float* __restrict__ out_scalars) {
    const int b = blockIdx.x;
    const int tid = threadIdx.x;
    __shared__ int sh_red[256];
    __shared__ unsigned char sh_hard[LDIM];
    __shared__ int sh_scan[256];
    __shared__ int sh_len;
    __shared__ int sh_count[NSEG];

    const float* mb = mask + b * LDIM;
    int ls = 0;
    for (int p = tid; p < LDIM; p += 256) ls += (mb[p] > 0.5f) ? 1 : 0;
    sh_red[tid] = ls;
    __syncthreads();
    for (int o = 128; o > 0; o >>= 1) {
        if (tid < o) sh_red[tid] += sh_red[tid + o];
        __syncthreads();
    }
    if (tid == 0) sh_len = sh_red[0];
    __syncthreads();
    const int len = sh_len;

    for (int p = tid; p < LDIM; p += 256) {
        int bit = (p >= 2 && p < len && g_logits[b * LDIM + p] > 0.f) ? 1 : 0;
        sh_hard[p] = (unsigned char)bit;
    }
    __syncthreads();
    if (tid == 0 && len < LDIM) sh_hard[len - 1] = 1;
    for (int s = tid; s < NSEG; s += 256) sh_count[s] = 0;
    __syncthreads();

    const int base = tid * 8;
    int t = 0;
    for (int q = 0; q < 8; q++) t += sh_hard[base + q];
    sh_scan[tid] = t;
    __syncthreads();
    for (int o = 1; o < 256; o <<= 1) {
        int v = sh_scan[tid];
        int u = (tid >= o) ? sh_scan[tid - o] : 0;
        __syncthreads();
        sh_scan[tid] = v + u;
        __syncthreads();
    }
    const int nb = sh_scan[255];
    int run = sh_scan[tid] - t;
    for (int q = 0; q < 8; q++) {
        int p = base + q;
        g_seg[b * LDIM + p] = (unsigned short)run;
        if (p < len && run < NSEG) atomicAdd(&sh_count[run], 1);
        run += sh_hard[p];
    }
    __syncthreads();
    for (int s = tid; s < NSEG; s += 256) g_count[b * NSEG + s] = sh_count[s];
    for (int s = tid; s < NSEG; s += 256) out_short[b * NSEG + s] = (s < nb) ? 1.f : 0.f;
    if (tid == 0) {
        g_len[b] = len;
        atomicAdd(&out_scalars[0], (float)nb);
        atomicAdd(&out_scalars[1], (float)len);
    }
}

// ---------------- segment-sum pooling (R7-exact, balanced) ----------------
__global__ __launch_bounds__(256) void k_pool(const float* __restrict__ hidden,
                                              float* __restrict__ pooled) {
    const int b = blockIdx.y;
    const int c0 = blockIdx.x * 128;
    const int tid = threadIdx.x;
    __shared__ unsigned short sseg[128];
    const int len = g_len[b];
    if (c0 >= len) return;
    if (tid < 128) sseg[tid] = g_seg[b * LDIM + c0 + tid];
    __syncthreads();

    const int d = tid * 4;
    const float* hb = hidden + ((size_t)b * LDIM + c0) * DDIM + d;
    float4 acc = make_float4(0.f, 0.f, 0.f, 0.f);
    int cur = sseg[0];
    const int lim = min(128, len - c0);
    for (int li = 0; li < lim; li++) {
        int s = sseg[li];
        if (s != cur) {
            if (cur < NSEG) {
                float* pp = pooled + ((size_t)b * NSEG + cur) * DDIM + d;
                atomicAdd(pp + 0, acc.x); atomicAdd(pp + 1, acc.y);
                atomicAdd(pp + 2, acc.z); atomicAdd(pp + 3, acc.w);
            }
            acc = make_float4(0.f, 0.f, 0.f, 0.f);
            cur = s;
        }
        float4 v = *(const float4*)(hb + (size_t)li * DDIM);
        acc.x += v.x; acc.y += v.y; acc.z += v.z; acc.w += v.w;
    }
    if (cur < NSEG) {
        float* pp = pooled + ((size_t)b * NSEG + cur) * DDIM + d;
        atomicAdd(pp + 0, acc.x); atomicAdd(pp + 1, acc.y);
        atomicAdd(pp + 2, acc.z); atomicAdd(pp + 3, acc.w);
    }
}

// ---------------- finalize: mean + PE ----------------
__global__ void k_final(float* __restrict__ out) {
    int idx = blockIdx.x * blockDim.x + threadIdx.x;
    if (idx < BDIM * NSEG * DDIM) {
        int sd = idx & (NSEG * DDIM - 1);
        int s = (idx >> 10) & (NSEG - 1);
        int b = idx >> 19;
        int cnt = g_count[b * NSEG + s];
        out[idx] = out[idx] / ((float)cnt + 1e-9f) + g_pe[sd];
    }
}

// ---------------- launch ----------------
extern "C" void kernel_launch(void* const* d_in, const int* in_sizes, int n_in,
                              void* d_out, int out_size) {
    const float* hidden = (const float*)d_in[0];
    const float* amask  = (const float*)d_in[1];
    const float* w1     = (const float*)d_in[2];
    const float* b1     = (const float*)d_in[3];
    const float* w2     = (const float*)d_in[4];
    const float* b2     = (const float*)d_in[5];
    float* out = (float*)d_out;

    const int pooled_n = BDIM * NSEG * DDIM;
    float* out_scalars = out + (out_size - BDIM * NSEG - 2);
    float* out_short   = out + (out_size - BDIM * NSEG);

    const int smem_bytes = 98304;   // 3 stages x 32KB
    cudaFuncSetAttribute(k_conv, cudaFuncAttributeMaxDynamicSharedMemorySize, smem_bytes);

    k_setup<<<(pooled_n + 2 + 255) / 256, 256>>>(hidden, out, pooled_n + 2, w1, b1, w2);
    k_conv<<<dim3(16, 3, BDIM), 256, smem_bytes>>>(nullptr);
    k_flag<<<(BDIM * (LDIM - 2) + 255) / 256, 256>>>(b2);
    k_fix<<<64, 256>>>(hidden, w1, b1, w2, b2);
    k_scan<<<BDIM, 256>>>(amask, out_short, out_scalars);
    k_pool<<<dim3(16, BDIM), 256>>>(hidden, out);
    k_final<<<(pooled_n + 255) / 256, 256>>>(out);
}